// round 3
// baseline (speedup 1.0000x reference)
#include <cuda_runtime.h>
#include <math.h>

#define BB 32768
#define SS 512
#define NH1 400
#define NH2 300
#define NAOUT 8
#define NSAMP 3

typedef unsigned long long u64t;

// packed f32x2 helpers (SASS FFMA2 / FMUL2 — only reachable via PTX)
static __device__ __forceinline__ void fma2(u64t &d, u64t a, u64t b) {
    asm("fma.rn.f32x2 %0, %1, %2, %0;" : "+l"(d) : "l"(a), "l"(b));
}
static __device__ __forceinline__ u64t mul2(u64t a, u64t b) {
    u64t d;
    asm("mul.rn.f32x2 %0, %1, %2;" : "=l"(d) : "l"(a), "l"(b));
    return d;
}
static __device__ __forceinline__ u64t dup2(float f) {
    u64t d;
    unsigned u = __float_as_uint(f);
    asm("mov.b64 %0, {%1, %1};" : "=l"(d) : "r"(u));
    return d;
}
static __device__ __forceinline__ void unpack2(u64t p, float &lo, float &hi) {
    unsigned a, b;
    asm("mov.b64 {%0, %1}, %2;" : "=r"(a), "=r"(b) : "l"(p));
    lo = __uint_as_float(a);
    hi = __uint_as_float(b);
}

// ---------------- scratch (static device globals; no allocation) ----------------
static __device__ float g_m1[(size_t)BB * NH1];
static __device__ float g_v1[(size_t)BB * NH1];
static __device__ float g_m2[(size_t)NSAMP * BB * NH2];
static __device__ float g_v2[(size_t)NSAMP * BB * NH2];
static __device__ unsigned g_min_u, g_max_u;
static __device__ float g_s1[NH1];   // rowsum(W1)
static __device__ float g_c1[NH1];   // 2.0001 * rowsum(W1^2)

static __device__ __forceinline__ unsigned fkey(float f) {
    unsigned u = __float_as_uint(f);
    return (u & 0x80000000u) ? ~u : (u | 0x80000000u);
}
static __device__ __forceinline__ float funkey(unsigned u) {
    return __uint_as_float((u & 0x80000000u) ? (u ^ 0x80000000u) : ~u);
}

static __device__ __forceinline__ void adf_relu(float m, float v, float &om, float &ov) {
    float sd  = sqrtf(v);
    float r   = m / sd;
    float cdf = 0.5f * (1.0f + erff(r * 0.7071067811865476f));
    float pdf = 0.3989422804014327f * expf(-0.5f * r * r);
    float o   = m * cdf + sd * pdf;
    om = o;
    ov = (m * m + v) * cdf + m * sd * pdf - o * o;
}

// ---------------- kernel 0: reset reduction state ----------------
__global__ void k_init() {
    g_min_u = 0xFFFFFFFFu;
    g_max_u = 0u;
}

// ---------------- kernel 1: global min/max of x ----------------
__global__ __launch_bounds__(256) void k_minmax(const float4 *__restrict__ x, int n4) {
    unsigned lmin = 0xFFFFFFFFu, lmax = 0u;
    for (int i = blockIdx.x * blockDim.x + threadIdx.x; i < n4; i += gridDim.x * blockDim.x) {
        float4 v = x[i];
        unsigned k0 = fkey(v.x), k1 = fkey(v.y), k2 = fkey(v.z), k3 = fkey(v.w);
        lmin = min(lmin, min(min(k0, k1), min(k2, k3)));
        lmax = max(lmax, max(max(k0, k1), max(k2, k3)));
    }
    lmin = __reduce_min_sync(0xFFFFFFFFu, lmin);
    lmax = __reduce_max_sync(0xFFFFFFFFu, lmax);
    __shared__ unsigned smin[8], smax[8];
    int wid = threadIdx.x >> 5, lane = threadIdx.x & 31;
    if (lane == 0) { smin[wid] = lmin; smax[wid] = lmax; }
    __syncthreads();
    if (threadIdx.x == 0) {
        unsigned m = smin[0], M = smax[0];
        #pragma unroll
        for (int i = 1; i < 8; i++) { m = min(m, smin[i]); M = max(M, smax[i]); }
        atomicMin(&g_min_u, m);
        atomicMax(&g_max_u, M);
    }
}

// ---------------- kernel 2: W1 row stats ----------------
__global__ __launch_bounds__(128) void k_w1stats(const float *__restrict__ W1) {
    int h = blockIdx.x;
    const float *row = W1 + (size_t)h * SS;
    float s = 0.f, q = 0.f;
    for (int k = threadIdx.x; k < SS; k += 128) {
        float w = row[k];
        s += w;
        q += w * w;
    }
    #pragma unroll
    for (int o = 16; o; o >>= 1) {
        s += __shfl_xor_sync(0xFFFFFFFFu, s, o);
        q += __shfl_xor_sync(0xFFFFFFFFu, q, o);
    }
    __shared__ float ss[4], qq[4];
    int wid = threadIdx.x >> 5;
    if ((threadIdx.x & 31) == 0) { ss[wid] = s; qq[wid] = q; }
    __syncthreads();
    if (threadIdx.x == 0) {
        g_s1[h] = ss[0] + ss[1] + ss[2] + ss[3];
        g_c1[h] = 2.0001f * (qq[0] + qq[1] + qq[2] + qq[3]);
    }
}

// ---------------- kernel 3: GEMM1 (x @ W1^T) + affine + bias + ADF ReLU ----------------
// BM=128, BN=64, BK=16, 256 threads, TM=8, TN=4; FFMA2 inner product
__global__ __launch_bounds__(256) void k_gemm1(const float *__restrict__ x,
                                               const float *__restrict__ W1,
                                               const float *__restrict__ b1) {
    __shared__ float As[16 * 128];
    __shared__ float Bs[16 * 64];
    int tid = threadIdx.x;
    int tx = tid & 15, ty = tid >> 4;
    int rowBase = blockIdx.x * 128;
    int colBase = blockIdx.y * 64;

    // accp[p][j] = (acc[2p][j], acc[2p+1][j]) packed f32x2
    u64t accp[4][4];
    #pragma unroll
    for (int p = 0; p < 4; p++)
        #pragma unroll
        for (int j = 0; j < 4; j++) accp[p][j] = 0ull;

    int ar = tid >> 2;
    int ak = (tid & 3) * 4;

    for (int k0 = 0; k0 < SS; k0 += 16) {
        float4 a0 = *(const float4 *)(x + (size_t)(rowBase + ar) * SS + k0 + ak);
        float4 a1 = *(const float4 *)(x + (size_t)(rowBase + ar + 64) * SS + k0 + ak);
        int j = colBase + ar;
        float4 b0 = make_float4(0.f, 0.f, 0.f, 0.f);
        if (j < NH1) b0 = *(const float4 *)(W1 + (size_t)j * SS + k0 + ak);
        __syncthreads();
        As[(ak + 0) * 128 + ar] = a0.x;
        As[(ak + 1) * 128 + ar] = a0.y;
        As[(ak + 2) * 128 + ar] = a0.z;
        As[(ak + 3) * 128 + ar] = a0.w;
        As[(ak + 0) * 128 + ar + 64] = a1.x;
        As[(ak + 1) * 128 + ar + 64] = a1.y;
        As[(ak + 2) * 128 + ar + 64] = a1.z;
        As[(ak + 3) * 128 + ar + 64] = a1.w;
        Bs[(ak + 0) * 64 + ar] = b0.x;
        Bs[(ak + 1) * 64 + ar] = b0.y;
        Bs[(ak + 2) * 64 + ar] = b0.z;
        Bs[(ak + 3) * 64 + ar] = b0.w;
        __syncthreads();
        #pragma unroll
        for (int kk = 0; kk < 16; kk++) {
            ulonglong2 A0 = *(ulonglong2 *)&As[kk * 128 + ty * 8];
            ulonglong2 A1 = *(ulonglong2 *)&As[kk * 128 + ty * 8 + 4];
            float4 tb = *(float4 *)&Bs[kk * 64 + tx * 4];
            u64t rap[4] = {A0.x, A0.y, A1.x, A1.y};
            u64t rb[4] = {dup2(tb.x), dup2(tb.y), dup2(tb.z), dup2(tb.w)};
            #pragma unroll
            for (int p = 0; p < 4; p++)
                #pragma unroll
                for (int jj = 0; jj < 4; jj++) fma2(accp[p][jj], rap[p], rb[jj]);
        }
    }

    float acc[8][4];
    #pragma unroll
    for (int p = 0; p < 4; p++)
        #pragma unroll
        for (int j = 0; j < 4; j++) unpack2(accp[p][j], acc[2 * p][j], acc[2 * p + 1][j]);

    float fmin = funkey(g_min_u);
    float fmax = funkey(g_max_u);
    float a_ = 1.0f / (fmax - fmin);
    float c_ = 0.1f - fmin * a_;

    int col = colBase + tx * 4;
    if (col < NH1) {
        #pragma unroll
        for (int i = 0; i < 8; i++) {
            int r = rowBase + ty * 8 + i;
            float4 om4, ov4;
            float *omp = &om4.x, *ovp = &ov4.x;
            #pragma unroll
            for (int jj = 0; jj < 4; jj++) {
                int h = col + jj;
                float m = a_ * acc[i][jj] + c_ * g_s1[h] + b1[h];
                float v = g_c1[h];
                float om, ov;
                adf_relu(m, v, om, ov);
                omp[jj] = om;
                ovp[jj] = ov;
            }
            *(float4 *)&g_m1[(size_t)r * NH1 + col] = om4;
            *(float4 *)&g_v1[(size_t)r * NH1 + col] = ov4;
        }
    }
}

// ---------------- kernel 4: GEMM2 dual (m & v) per sample + ADF + mask2 ----------------
// BM=128, BN=64, BK=16, 256 threads, TM=8, TN=4, grid.z = sample; FFMA2 inner product
__global__ __launch_bounds__(256) void k_gemm2(const float *__restrict__ W2,
                                               const float *__restrict__ b2,
                                               const float *__restrict__ mask1,
                                               const float *__restrict__ mask2) {
    __shared__ float Am[16 * 128];
    __shared__ float Av[16 * 128];
    __shared__ float Bs[16 * 64];
    int tid = threadIdx.x;
    int tx = tid & 15, ty = tid >> 4;
    int rowBase = blockIdx.x * 128;
    int colBase = blockIdx.y * 64;
    int n = blockIdx.z;
    const float *mkp = mask1 + (size_t)n * BB * NH1;

    u64t accm[4][4], accv[4][4];
    #pragma unroll
    for (int p = 0; p < 4; p++)
        #pragma unroll
        for (int j = 0; j < 4; j++) { accm[p][j] = 0ull; accv[p][j] = 0ull; }

    int ar = tid >> 2;
    int ak = (tid & 3) * 4;

    for (int k0 = 0; k0 < NH1; k0 += 16) {
        size_t o0 = (size_t)(rowBase + ar) * NH1 + k0 + ak;
        size_t o1 = (size_t)(rowBase + ar + 64) * NH1 + k0 + ak;
        float4 m0 = *(const float4 *)(g_m1 + o0);
        float4 v0 = *(const float4 *)(g_v1 + o0);
        float4 q0 = *(const float4 *)(mkp + o0);
        float4 m1r = *(const float4 *)(g_m1 + o1);
        float4 v1r = *(const float4 *)(g_v1 + o1);
        float4 q1 = *(const float4 *)(mkp + o1);
        int j = colBase + ar;
        float4 w = make_float4(0.f, 0.f, 0.f, 0.f);
        if (j < NH2) w = *(const float4 *)(W2 + (size_t)j * NH1 + k0 + ak);
        __syncthreads();
        Am[(ak + 0) * 128 + ar] = m0.x * q0.x;
        Am[(ak + 1) * 128 + ar] = m0.y * q0.y;
        Am[(ak + 2) * 128 + ar] = m0.z * q0.z;
        Am[(ak + 3) * 128 + ar] = m0.w * q0.w;
        Av[(ak + 0) * 128 + ar] = v0.x * q0.x * q0.x;
        Av[(ak + 1) * 128 + ar] = v0.y * q0.y * q0.y;
        Av[(ak + 2) * 128 + ar] = v0.z * q0.z * q0.z;
        Av[(ak + 3) * 128 + ar] = v0.w * q0.w * q0.w;
        Am[(ak + 0) * 128 + ar + 64] = m1r.x * q1.x;
        Am[(ak + 1) * 128 + ar + 64] = m1r.y * q1.y;
        Am[(ak + 2) * 128 + ar + 64] = m1r.z * q1.z;
        Am[(ak + 3) * 128 + ar + 64] = m1r.w * q1.w;
        Av[(ak + 0) * 128 + ar + 64] = v1r.x * q1.x * q1.x;
        Av[(ak + 1) * 128 + ar + 64] = v1r.y * q1.y * q1.y;
        Av[(ak + 2) * 128 + ar + 64] = v1r.z * q1.z * q1.z;
        Av[(ak + 3) * 128 + ar + 64] = v1r.w * q1.w * q1.w;
        Bs[(ak + 0) * 64 + ar] = w.x;
        Bs[(ak + 1) * 64 + ar] = w.y;
        Bs[(ak + 2) * 64 + ar] = w.z;
        Bs[(ak + 3) * 64 + ar] = w.w;
        __syncthreads();
        #pragma unroll
        for (int kk = 0; kk < 16; kk++) {
            ulonglong2 M0 = *(ulonglong2 *)&Am[kk * 128 + ty * 8];
            ulonglong2 M1 = *(ulonglong2 *)&Am[kk * 128 + ty * 8 + 4];
            ulonglong2 V0 = *(ulonglong2 *)&Av[kk * 128 + ty * 8];
            ulonglong2 V1 = *(ulonglong2 *)&Av[kk * 128 + ty * 8 + 4];
            float4 tb = *(float4 *)&Bs[kk * 64 + tx * 4];
            u64t ramp[4] = {M0.x, M0.y, M1.x, M1.y};
            u64t ravp[4] = {V0.x, V0.y, V1.x, V1.y};
            u64t rb[4] = {dup2(tb.x), dup2(tb.y), dup2(tb.z), dup2(tb.w)};
            u64t rb2[4] = {mul2(rb[0], rb[0]), mul2(rb[1], rb[1]),
                           mul2(rb[2], rb[2]), mul2(rb[3], rb[3])};
            #pragma unroll
            for (int p = 0; p < 4; p++)
                #pragma unroll
                for (int jj = 0; jj < 4; jj++) {
                    fma2(accm[p][jj], ramp[p], rb[jj]);
                    fma2(accv[p][jj], ravp[p], rb2[jj]);
                }
        }
    }

    float am[8][4], av[8][4];
    #pragma unroll
    for (int p = 0; p < 4; p++)
        #pragma unroll
        for (int j = 0; j < 4; j++) {
            unpack2(accm[p][j], am[2 * p][j], am[2 * p + 1][j]);
            unpack2(accv[p][j], av[2 * p][j], av[2 * p + 1][j]);
        }

    int col = colBase + tx * 4;
    if (col < NH2) {
        #pragma unroll
        for (int i = 0; i < 8; i++) {
            int r = rowBase + ty * 8 + i;
            size_t base = ((size_t)n * BB + r) * NH2 + col;
            float4 mk = *(const float4 *)(mask2 + base);
            float *mkp4 = &mk.x;
            float4 om4, ov4;
            float *omp = &om4.x, *ovp = &ov4.x;
            #pragma unroll
            for (int jj = 0; jj < 4; jj++) {
                float m = am[i][jj] + b2[col + jj];
                float v = av[i][jj];
                float om, ov;
                adf_relu(m, v, om, ov);
                float q = mkp4[jj];
                omp[jj] = om * q;
                ovp[jj] = ov * q * q;
            }
            *(float4 *)&g_m2[base] = om4;
            *(float4 *)&g_v2[base] = ov4;
        }
    }
}

// ---------------- kernel 5: layer3 + MC statistics + 10^var ----------------
__global__ __launch_bounds__(256) void k_final(const float *__restrict__ W3,
                                               const float *__restrict__ b3,
                                               float *__restrict__ out) {
    __shared__ float w3s[NAOUT * NH2];
    __shared__ float w3s2[NAOUT * NH2];
    __shared__ float b3s[NAOUT];
    int tid = threadIdx.x;
    for (int i = tid; i < NAOUT * NH2; i += 256) {
        float w = W3[i];
        w3s[i] = w;
        w3s2[i] = w * w;
    }
    if (tid < NAOUT) b3s[tid] = b3[tid];
    __syncthreads();

    int warp = tid >> 5, lane = tid & 31;
    size_t b = (size_t)blockIdx.x * 8 + warp;

    float am[NSAMP][NAOUT], av[NSAMP][NAOUT];
    #pragma unroll
    for (int n = 0; n < NSAMP; n++)
        #pragma unroll
        for (int a = 0; a < NAOUT; a++) { am[n][a] = 0.f; av[n][a] = 0.f; }

    for (int j = lane; j < NH2; j += 32) {
        float w[NAOUT], w2[NAOUT];
        #pragma unroll
        for (int a = 0; a < NAOUT; a++) {
            w[a] = w3s[a * NH2 + j];
            w2[a] = w3s2[a * NH2 + j];
        }
        #pragma unroll
        for (int n = 0; n < NSAMP; n++) {
            size_t off = ((size_t)n * BB + b) * NH2 + j;
            float mf = g_m2[off];
            float vf = g_v2[off];
            #pragma unroll
            for (int a = 0; a < NAOUT; a++) {
                am[n][a] += mf * w[a];
                av[n][a] += vf * w2[a];
            }
        }
    }
    #pragma unroll
    for (int n = 0; n < NSAMP; n++)
        #pragma unroll
        for (int a = 0; a < NAOUT; a++)
            #pragma unroll
            for (int o = 16; o; o >>= 1) {
                am[n][a] += __shfl_xor_sync(0xFFFFFFFFu, am[n][a], o);
                av[n][a] += __shfl_xor_sync(0xFFFFFFFFu, av[n][a], o);
            }

    if (lane == 0) {
        #pragma unroll
        for (int a = 0; a < NAOUT; a++) {
            float s1 = 0.f, s2 = 0.f, sv = 0.f;
            #pragma unroll
            for (int n = 0; n < NSAMP; n++) {
                float m3 = am[n][a] + b3s[a];
                s1 += m3;
                s2 += m3 * m3;
                sv += av[n][a];
            }
            const float inv3 = 1.0f / 3.0f;
            float mean = s1 * inv3;
            float var = sv * inv3 + s2 * inv3 - mean * mean;
            out[b * NAOUT + a] = mean;
            out[(size_t)BB * NAOUT + b * NAOUT + a] = exp10f(var);
        }
    }
}

// ---------------- launch ----------------
extern "C" void kernel_launch(void *const *d_in, const int *in_sizes, int n_in,
                              void *d_out, int out_size) {
    const float *x  = (const float *)d_in[0];
    const float *W1 = (const float *)d_in[2];
    const float *b1 = (const float *)d_in[3];
    const float *W2 = (const float *)d_in[4];
    const float *b2 = (const float *)d_in[5];
    const float *W3 = (const float *)d_in[6];
    const float *b3 = (const float *)d_in[7];
    const float *mask1 = (const float *)d_in[8];
    const float *mask2 = (const float *)d_in[9];
    float *out = (float *)d_out;

    k_init<<<1, 1>>>();
    k_minmax<<<2048, 256>>>((const float4 *)x, BB * SS / 4);
    k_w1stats<<<NH1, 128>>>(W1);
    dim3 g1(BB / 128, (NH1 + 63) / 64);
    k_gemm1<<<g1, 256>>>(x, W1, b1);
    dim3 g2(BB / 128, (NH2 + 63) / 64, NSAMP);
    k_gemm2<<<g2, 256>>>(W2, b2, mask1, mask2);
    k_final<<<BB / 8, 256>>>(W3, b3, out);
}

// round 14
// speedup vs baseline: 1.0771x; 1.0771x over previous
#include <cuda_runtime.h>
#include <cuda_bf16.h>
#include <math.h>
#include <stdint.h>

#define BB 32768
#define SS 512
#define NH1 400
#define NH2 300
#define NAOUT 8
#define NSAMP 3
#define KPAD 448
#define NB 64        // cols per CTA
#define NBLK 5       // 5*64 = 320 >= 300
#define NROWS 320
#define NCH 25       // 25*16 = 400 = NH1 exactly

typedef unsigned long long u64t;

// ---------------- scratch ----------------
static __device__ float g_m1[(size_t)BB * NH1];
static __device__ float g_v1[(size_t)BB * NH1];
static __device__ __nv_bfloat16 g_W2h[NROWS * KPAD];
static __device__ __nv_bfloat16 g_W2l[NROWS * KPAD];
static __device__ __nv_bfloat16 g_W2qh[NROWS * KPAD];
static __device__ __nv_bfloat16 g_W2ql[NROWS * KPAD];
static __device__ float g_Pm[(size_t)NSAMP * NBLK * BB * NAOUT];
static __device__ float g_Pv[(size_t)NSAMP * NBLK * BB * NAOUT];
static __device__ unsigned g_min_u, g_max_u;
static __device__ float g_s1[NH1];
static __device__ float g_c1[NH1];

static __device__ __forceinline__ unsigned fkey(float f) {
    unsigned u = __float_as_uint(f);
    return (u & 0x80000000u) ? ~u : (u | 0x80000000u);
}
static __device__ __forceinline__ float funkey(unsigned u) {
    return __uint_as_float((u & 0x80000000u) ? (u ^ 0x80000000u) : ~u);
}
static __device__ __forceinline__ void adf_relu(float m, float v, float &om, float &ov) {
    float sd  = sqrtf(v);
    float r   = m / sd;
    float cdf = 0.5f * (1.0f + erff(r * 0.7071067811865476f));
    float pdf = 0.3989422804014327f * expf(-0.5f * r * r);
    float o   = m * cdf + sd * pdf;
    om = o;
    ov = (m * m + v) * cdf + m * sd * pdf - o * o;
}
static __device__ __forceinline__ unsigned bfpack(float x, float y) {
    __nv_bfloat162 t = __floats2bfloat162_rn(x, y);
    return *(unsigned *)&t;
}
static __device__ __forceinline__ float bfi(float x) {
    return __bfloat162float(__float2bfloat16_rn(x));
}
static __device__ __forceinline__ void fma2(u64t &d, u64t a, u64t b) {
    asm("fma.rn.f32x2 %0, %1, %2, %0;" : "+l"(d) : "l"(a), "l"(b));
}
static __device__ __forceinline__ u64t dup2(float f) {
    u64t d; unsigned u = __float_as_uint(f);
    asm("mov.b64 %0, {%1, %1};" : "=l"(d) : "r"(u));
    return d;
}
static __device__ __forceinline__ void unpack2(u64t p, float &lo, float &hi) {
    unsigned a, b;
    asm("mov.b64 {%0, %1}, %2;" : "=r"(a), "=r"(b) : "l"(p));
    lo = __uint_as_float(a); hi = __uint_as_float(b);
}

// bf16 warp MMA: D(16x8,f32) += A(16x16,bf16,row) * B(8x16,bf16 [n][k])
static __device__ __forceinline__ void hmma(float *d, const unsigned *a, const unsigned *b) {
    asm volatile("mma.sync.aligned.m16n8k16.row.col.f32.bf16.bf16.f32 "
        "{%0,%1,%2,%3}, {%4,%5,%6,%7}, {%8,%9}, {%0,%1,%2,%3};"
        : "+f"(d[0]), "+f"(d[1]), "+f"(d[2]), "+f"(d[3])
        : "r"(a[0]), "r"(a[1]), "r"(a[2]), "r"(a[3]), "r"(b[0]), "r"(b[1]));
}

// ---------------- small kernels ----------------
__global__ void k_init() { g_min_u = 0xFFFFFFFFu; g_max_u = 0u; }

__global__ __launch_bounds__(256) void k_minmax(const float4 *__restrict__ x, int n4) {
    unsigned lmin = 0xFFFFFFFFu, lmax = 0u;
    for (int i = blockIdx.x * blockDim.x + threadIdx.x; i < n4; i += gridDim.x * blockDim.x) {
        float4 v = x[i];
        unsigned k0 = fkey(v.x), k1 = fkey(v.y), k2 = fkey(v.z), k3 = fkey(v.w);
        lmin = min(lmin, min(min(k0, k1), min(k2, k3)));
        lmax = max(lmax, max(max(k0, k1), max(k2, k3)));
    }
    lmin = __reduce_min_sync(0xFFFFFFFFu, lmin);
    lmax = __reduce_max_sync(0xFFFFFFFFu, lmax);
    __shared__ unsigned smin[8], smax[8];
    int wid = threadIdx.x >> 5, lane = threadIdx.x & 31;
    if (lane == 0) { smin[wid] = lmin; smax[wid] = lmax; }
    __syncthreads();
    if (threadIdx.x == 0) {
        unsigned m = smin[0], M = smax[0];
        #pragma unroll
        for (int i = 1; i < 8; i++) { m = min(m, smin[i]); M = max(M, smax[i]); }
        atomicMin(&g_min_u, m);
        atomicMax(&g_max_u, M);
    }
}

__global__ __launch_bounds__(128) void k_w1stats(const float *__restrict__ W1) {
    int h = blockIdx.x;
    const float *row = W1 + (size_t)h * SS;
    float s = 0.f, q = 0.f;
    for (int k = threadIdx.x; k < SS; k += 128) { float w = row[k]; s += w; q += w * w; }
    #pragma unroll
    for (int o = 16; o; o >>= 1) {
        s += __shfl_xor_sync(0xFFFFFFFFu, s, o);
        q += __shfl_xor_sync(0xFFFFFFFFu, q, o);
    }
    __shared__ float ss[4], qq[4];
    int wid = threadIdx.x >> 5;
    if ((threadIdx.x & 31) == 0) { ss[wid] = s; qq[wid] = q; }
    __syncthreads();
    if (threadIdx.x == 0) {
        g_s1[h] = ss[0] + ss[1] + ss[2] + ss[3];
        g_c1[h] = 2.0001f * (qq[0] + qq[1] + qq[2] + qq[3]);
    }
}

__global__ __launch_bounds__(256) void k_w2split(const float *__restrict__ W2) {
    int idx = blockIdx.x * 256 + threadIdx.x;
    if (idx >= NROWS * KPAD) return;
    int j = idx / KPAD, k = idx % KPAD;
    float w = (j < NH2 && k < NH1) ? W2[j * NH1 + k] : 0.f;
    float wq = w * w;
    g_W2h[idx]  = __float2bfloat16_rn(w);
    g_W2l[idx]  = __float2bfloat16_rn(w - bfi(w));
    g_W2qh[idx] = __float2bfloat16_rn(wq);
    g_W2ql[idx] = __float2bfloat16_rn(wq - bfi(wq));
}

// ---------------- GEMM1 (SIMT FFMA2, proven 363us) ----------------
__global__ __launch_bounds__(256) void k_gemm1(const float *__restrict__ x,
                                               const float *__restrict__ W1,
                                               const float *__restrict__ b1) {
    __shared__ float As[16 * 128];
    __shared__ float Bs[16 * 64];
    int tid = threadIdx.x;
    int tx = tid & 15, ty = tid >> 4;
    int rowBase = blockIdx.x * 128;
    int colBase = blockIdx.y * 64;

    u64t accp[4][4];
    #pragma unroll
    for (int p = 0; p < 4; p++)
        #pragma unroll
        for (int j = 0; j < 4; j++) accp[p][j] = 0ull;

    int ar = tid >> 2;
    int ak = (tid & 3) * 4;

    for (int k0 = 0; k0 < SS; k0 += 16) {
        float4 a0 = *(const float4 *)(x + (size_t)(rowBase + ar) * SS + k0 + ak);
        float4 a1 = *(const float4 *)(x + (size_t)(rowBase + ar + 64) * SS + k0 + ak);
        int j = colBase + ar;
        float4 b0 = make_float4(0.f, 0.f, 0.f, 0.f);
        if (j < NH1) b0 = *(const float4 *)(W1 + (size_t)j * SS + k0 + ak);
        __syncthreads();
        As[(ak + 0) * 128 + ar] = a0.x;
        As[(ak + 1) * 128 + ar] = a0.y;
        As[(ak + 2) * 128 + ar] = a0.z;
        As[(ak + 3) * 128 + ar] = a0.w;
        As[(ak + 0) * 128 + ar + 64] = a1.x;
        As[(ak + 1) * 128 + ar + 64] = a1.y;
        As[(ak + 2) * 128 + ar + 64] = a1.z;
        As[(ak + 3) * 128 + ar + 64] = a1.w;
        Bs[(ak + 0) * 64 + ar] = b0.x;
        Bs[(ak + 1) * 64 + ar] = b0.y;
        Bs[(ak + 2) * 64 + ar] = b0.z;
        Bs[(ak + 3) * 64 + ar] = b0.w;
        __syncthreads();
        #pragma unroll
        for (int kk = 0; kk < 16; kk++) {
            ulonglong2 A0 = *(ulonglong2 *)&As[kk * 128 + ty * 8];
            ulonglong2 A1 = *(ulonglong2 *)&As[kk * 128 + ty * 8 + 4];
            float4 tb = *(float4 *)&Bs[kk * 64 + tx * 4];
            u64t rap[4] = {A0.x, A0.y, A1.x, A1.y};
            u64t rb[4] = {dup2(tb.x), dup2(tb.y), dup2(tb.z), dup2(tb.w)};
            #pragma unroll
            for (int p = 0; p < 4; p++)
                #pragma unroll
                for (int jj = 0; jj < 4; jj++) fma2(accp[p][jj], rap[p], rb[jj]);
        }
    }

    float acc[8][4];
    #pragma unroll
    for (int p = 0; p < 4; p++)
        #pragma unroll
        for (int j = 0; j < 4; j++) unpack2(accp[p][j], acc[2 * p][j], acc[2 * p + 1][j]);

    float fmin = funkey(g_min_u);
    float fmax = funkey(g_max_u);
    float a_ = 1.0f / (fmax - fmin);
    float c_ = 0.1f - fmin * a_;

    int col = colBase + tx * 4;
    if (col < NH1) {
        #pragma unroll
        for (int i = 0; i < 8; i++) {
            int r = rowBase + ty * 8 + i;
            float4 om4, ov4;
            float *omp = &om4.x, *ovp = &ov4.x;
            #pragma unroll
            for (int jj = 0; jj < 4; jj++) {
                int h = col + jj;
                float m = a_ * acc[i][jj] + c_ * g_s1[h] + b1[h];
                float om, ov;
                adf_relu(m, g_c1[h], om, ov);
                omp[jj] = om;
                ovp[jj] = ov;
            }
            *(float4 *)&g_m1[(size_t)r * NH1 + col] = om4;
            *(float4 *)&g_v1[(size_t)r * NH1 + col] = ov4;
        }
    }
}

// ---------------- GEMM2: warp MMA (mma.sync bf16, split hi/lo) ----------------
// SMEM (bytes). A tiles [128 rows][24 bf16] = 6144 each; B tiles [64][24] = 3072.
// Exchange region (post-mainloop) reuses A/B space: XV@0 (128*68*4), XM@34816.
#define AM_H  0
#define AM_L  6144
#define AV_H  12288
#define AV_L  18432
#define BS_H  24576
#define BS_L  27648
#define BS_QH 30720
#define BS_QL 33792
#define XV    0
#define XM    34816
#define SW3S  69632
#define SW3Q  71680
#define SB2S  73728
#define G2_SMEM 74240

__global__ __launch_bounds__(256, 2) void k_gemm2_mma(const float *__restrict__ mask1,
                                                      const float *__restrict__ mask2,
                                                      const float *__restrict__ b2,
                                                      const float *__restrict__ W3) {
    extern __shared__ char smem[];
    int tid = threadIdx.x, w = tid >> 5, l = tid & 31;
    int blk = blockIdx.x, n = blockIdx.y;
    int rowBase = blockIdx.z * 128, colBase = blk * NB;

    float *W3s = (float *)(smem + SW3S);
    float *W3q = (float *)(smem + SW3Q);
    float *b2s = (float *)(smem + SB2S);
    for (int i = tid; i < NAOUT * NB; i += 256) {
        int a = i >> 6, c = i & 63;
        float wv = (colBase + c < NH2) ? W3[a * NH2 + colBase + c] : 0.f;
        W3s[i] = wv;
        W3q[i] = wv * wv;
    }
    for (int c = tid; c < NB; c += 256)
        b2s[c] = (colBase + c < NH2) ? b2[colBase + c] : 0.f;

    // A producer: thread -> (row = tid/2, k-half = (tid&1)*8)
    int prow = tid >> 1, pkh = (tid & 1) * 8;
    const float *m1p = g_m1 + (size_t)(rowBase + prow) * NH1 + pkh;
    const float *v1p = g_v1 + (size_t)(rowBase + prow) * NH1 + pkh;
    const float *q1p = mask1 + ((size_t)n * BB + rowBase + prow) * NH1 + pkh;
    uint32_t pA = (uint32_t)(prow * 48 + pkh * 2);

    // B producer: thread -> (array = tid/64, brow = tid%64)
    int barr = tid >> 6, brow = tid & 63;
    const __nv_bfloat16 *bsrc;
    uint32_t bdst;
    {
        const __nv_bfloat16 *gs0 = (barr == 0) ? g_W2h : (barr == 1) ? g_W2l : (barr == 2) ? g_W2qh : g_W2ql;
        const uint32_t bd0 = (barr == 0) ? BS_H : (barr == 1) ? BS_L : (barr == 2) ? BS_QH : BS_QL;
        bsrc = gs0 + (size_t)(colBase + brow) * KPAD;
        bdst = bd0 + (uint32_t)(brow * 48);
    }

    int path = w >> 2, wr = w & 3;
    uint32_t aH = path ? AV_H : AM_H, aL = path ? AV_L : AM_L;
    uint32_t bH = path ? BS_QH : BS_H, bL = path ? BS_QL : BS_L;
    uint32_t fr = (uint32_t)(l >> 2), fc4 = (uint32_t)((l & 3) * 4);
    uint32_t aOff = (uint32_t)((wr * 32 + fr) * 48) + fc4;   // + mt*768
    uint32_t bOff = fr * 48 + fc4;                            // + ct*384

    float acc[2][8][4];
    #pragma unroll
    for (int mt = 0; mt < 2; mt++)
        #pragma unroll
        for (int ct = 0; ct < 8; ct++)
            #pragma unroll
            for (int e = 0; e < 4; e++) acc[mt][ct][e] = 0.f;

    for (int ch = 0; ch < NCH; ch++) {
        // produce A (split bf16 of m1*q and v1*q^2)
        float m8[8], v8[8], q8[8];
        *(float4 *)&m8[0] = *(const float4 *)(m1p);
        *(float4 *)&m8[4] = *(const float4 *)(m1p + 4);
        *(float4 *)&v8[0] = *(const float4 *)(v1p);
        *(float4 *)&v8[4] = *(const float4 *)(v1p + 4);
        *(float4 *)&q8[0] = *(const float4 *)(q1p);
        *(float4 *)&q8[4] = *(const float4 *)(q1p + 4);
        m1p += 16; v1p += 16; q1p += 16;
        unsigned mh[4], ml[4], vh[4], vl[4];
        #pragma unroll
        for (int e = 0; e < 8; e += 2) {
            float a0 = m8[e] * q8[e], a1 = m8[e + 1] * q8[e + 1];
            float c0 = v8[e] * q8[e] * q8[e], c1 = v8[e + 1] * q8[e + 1] * q8[e + 1];
            int i2 = e >> 1;
            mh[i2] = bfpack(a0, a1);
            ml[i2] = bfpack(a0 - bfi(a0), a1 - bfi(a1));
            vh[i2] = bfpack(c0, c1);
            vl[i2] = bfpack(c0 - bfi(c0), c1 - bfi(c1));
        }
        *(uint4 *)(smem + AM_H + pA) = make_uint4(mh[0], mh[1], mh[2], mh[3]);
        *(uint4 *)(smem + AM_L + pA) = make_uint4(ml[0], ml[1], ml[2], ml[3]);
        *(uint4 *)(smem + AV_H + pA) = make_uint4(vh[0], vh[1], vh[2], vh[3]);
        *(uint4 *)(smem + AV_L + pA) = make_uint4(vl[0], vl[1], vl[2], vl[3]);
        // produce B (pre-split W2 / W2^2)
        {
            uint4 q0 = *(const uint4 *)(bsrc + ch * 16);
            uint4 q1 = *(const uint4 *)(bsrc + ch * 16 + 8);
            *(uint4 *)(smem + bdst) = q0;
            *(uint4 *)(smem + bdst + 16) = q1;
        }
        __syncthreads();
        // A fragments
        unsigned ah[2][4], al[2][4];
        #pragma unroll
        for (int mt = 0; mt < 2; mt++) {
            uint32_t ad = aOff + (uint32_t)(mt * 768);
            ah[mt][0] = *(unsigned *)(smem + aH + ad);
            ah[mt][1] = *(unsigned *)(smem + aH + ad + 384);
            ah[mt][2] = *(unsigned *)(smem + aH + ad + 16);
            ah[mt][3] = *(unsigned *)(smem + aH + ad + 400);
            al[mt][0] = *(unsigned *)(smem + aL + ad);
            al[mt][1] = *(unsigned *)(smem + aL + ad + 384);
            al[mt][2] = *(unsigned *)(smem + aL + ad + 16);
            al[mt][3] = *(unsigned *)(smem + aL + ad + 400);
        }
        #pragma unroll
        for (int ct = 0; ct < 8; ct++) {
            uint32_t bd = bOff + (uint32_t)(ct * 384);
            unsigned bhf[2], blf[2];
            bhf[0] = *(unsigned *)(smem + bH + bd);
            bhf[1] = *(unsigned *)(smem + bH + bd + 16);
            blf[0] = *(unsigned *)(smem + bL + bd);
            blf[1] = *(unsigned *)(smem + bL + bd + 16);
            #pragma unroll
            for (int mt = 0; mt < 2; mt++) {
                hmma(acc[mt][ct], ah[mt], bhf);
                hmma(acc[mt][ct], al[mt], bhf);
                hmma(acc[mt][ct], ah[mt], blf);
            }
        }
        __syncthreads();
    }

    // dump accumulators to exchange region (m -> XM, v -> XV)
    {
        float *Xp = (float *)(smem + (path ? XV : XM));
        #pragma unroll
        for (int mt = 0; mt < 2; mt++)
            #pragma unroll
            for (int ct = 0; ct < 8; ct++) {
                int r0 = wr * 32 + mt * 16 + (int)fr;
                int c0 = ct * 8 + (l & 3) * 2;
                *(float2 *)&Xp[r0 * 68 + c0] = make_float2(acc[mt][ct][0], acc[mt][ct][1]);
                *(float2 *)&Xp[(r0 + 8) * 68 + c0] = make_float2(acc[mt][ct][2], acc[mt][ct][3]);
            }
    }
    __syncthreads();

    // epilogue: warp w handles rows w*16..+15; lane: row = w*16 + l/2, col half = l&1
    {
        int erow = w * 16 + (l >> 1), ecol0 = (l & 1) * 32;
        const float *Xm = (const float *)(smem + XM);
        const float *Xv = (const float *)(smem + XV);
        const float *m2r = mask2 + ((size_t)n * BB + rowBase + erow) * NH2 + colBase;
        float pm[NAOUT], pv[NAOUT];
        #pragma unroll
        for (int a = 0; a < NAOUT; a++) { pm[a] = 0.f; pv[a] = 0.f; }
        #pragma unroll 4
        for (int c = 0; c < 32; c++) {
            int cc = ecol0 + c;
            if (colBase + cc < NH2) {
                float m = Xm[erow * 68 + cc] + b2s[cc];
                float v = Xv[erow * 68 + cc];
                float om, ov;
                adf_relu(m, v, om, ov);
                float q = __ldg(m2r + cc);
                float am = om * q, av = ov * q * q;
                #pragma unroll
                for (int a = 0; a < NAOUT; a++) {
                    pm[a] += am * W3s[a * NB + cc];
                    pv[a] += av * W3q[a * NB + cc];
                }
            }
        }
        #pragma unroll
        for (int a = 0; a < NAOUT; a++) {
            pm[a] += __shfl_xor_sync(0xFFFFFFFFu, pm[a], 1);
            pv[a] += __shfl_xor_sync(0xFFFFFFFFu, pv[a], 1);
        }
        if ((l & 1) == 0) {
            size_t base = (((size_t)n * NBLK + blk) * BB + rowBase + erow) * NAOUT;
            *(float4 *)&g_Pm[base + 0] = make_float4(pm[0], pm[1], pm[2], pm[3]);
            *(float4 *)&g_Pm[base + 4] = make_float4(pm[4], pm[5], pm[6], pm[7]);
            *(float4 *)&g_Pv[base + 0] = make_float4(pv[0], pv[1], pv[2], pv[3]);
            *(float4 *)&g_Pv[base + 4] = make_float4(pv[4], pv[5], pv[6], pv[7]);
        }
    }
}

// ---------------- final reduction ----------------
__global__ __launch_bounds__(256) void k_final(const float *__restrict__ b3,
                                               float *__restrict__ out) {
    int i = blockIdx.x * 256 + threadIdx.x;
    if (i >= BB * NAOUT) return;
    int b = i >> 3, a = i & 7;
    float s1 = 0.f, s2 = 0.f, sv = 0.f;
    float bb3 = b3[a];
    #pragma unroll
    for (int n = 0; n < NSAMP; n++) {
        float m3 = bb3, v3 = 0.f;
        #pragma unroll
        for (int blk = 0; blk < NBLK; blk++) {
            size_t idx = (((size_t)n * NBLK + blk) * BB + b) * NAOUT + a;
            m3 += g_Pm[idx];
            v3 += g_Pv[idx];
        }
        s1 += m3;
        s2 += m3 * m3;
        sv += v3;
    }
    const float inv3 = 1.0f / 3.0f;
    float mean = s1 * inv3;
    float var = sv * inv3 + s2 * inv3 - mean * mean;
    out[(size_t)b * NAOUT + a] = mean;
    out[(size_t)BB * NAOUT + (size_t)b * NAOUT + a] = exp10f(var);
}

// ---------------- launch ----------------
extern "C" void kernel_launch(void *const *d_in, const int *in_sizes, int n_in,
                              void *d_out, int out_size) {
    const float *x  = (const float *)d_in[0];
    const float *W1 = (const float *)d_in[2];
    const float *b1 = (const float *)d_in[3];
    const float *W2 = (const float *)d_in[4];
    const float *b2 = (const float *)d_in[5];
    const float *W3 = (const float *)d_in[6];
    const float *b3 = (const float *)d_in[7];
    const float *mask1 = (const float *)d_in[8];
    const float *mask2 = (const float *)d_in[9];
    float *out = (float *)d_out;

    cudaFuncSetAttribute(k_gemm2_mma, cudaFuncAttributeMaxDynamicSharedMemorySize, G2_SMEM);

    k_init<<<1, 1>>>();
    k_minmax<<<2048, 256>>>((const float4 *)x, BB * SS / 4);
    k_w1stats<<<NH1, 128>>>(W1);
    k_w2split<<<(NROWS * KPAD + 255) / 256, 256>>>(W2);
    dim3 g1(BB / 128, (NH1 + 63) / 64);
    k_gemm1<<<g1, 256>>>(x, W1, b1);
    dim3 g2(NBLK, NSAMP, BB / 128);
    k_gemm2_mma<<<g2, 256, G2_SMEM>>>(mask1, mask2, b2, W3);
    k_final<<<BB * NAOUT / 256, 256>>>(b3, out);
}

// round 16
// speedup vs baseline: 1.7488x; 1.6236x over previous
#include <cuda_runtime.h>
#include <cuda_bf16.h>
#include <math.h>
#include <stdint.h>

#define BB 32768
#define SS 512
#define NH1 400
#define NH2 300
#define NAOUT 8
#define NSAMP 3
#define KPAD 416      // 13 * 32
#define NB 64         // cols per CTA
#define NBLK 5        // 5*64 = 320 >= 300
#define NROWS 320
#define NCH 13        // K chunks of 32
#define KC 32
#define MWORDS 13     // mask words per row (416 bits)

typedef unsigned long long u64t;

// ---------------- scratch ----------------
static __device__ __nv_bfloat16 g_m1h[(size_t)BB * KPAD];
static __device__ __nv_bfloat16 g_m1l[(size_t)BB * KPAD];
static __device__ __nv_bfloat16 g_v1h[(size_t)BB * KPAD];
static __device__ __nv_bfloat16 g_v1l[(size_t)BB * KPAD];
static __device__ unsigned g_mk1[(size_t)NSAMP * BB * MWORDS];
static __device__ __nv_bfloat16 g_W2h[NROWS * KPAD];
static __device__ __nv_bfloat16 g_W2l[NROWS * KPAD];
static __device__ __nv_bfloat16 g_W2qh[NROWS * KPAD];
static __device__ __nv_bfloat16 g_W2ql[NROWS * KPAD];
static __device__ float g_Pm[(size_t)NSAMP * NBLK * BB * NAOUT];
static __device__ float g_Pv[(size_t)NSAMP * NBLK * BB * NAOUT];
static __device__ unsigned g_min_u, g_max_u;
static __device__ float g_s1[NH1];
static __device__ float g_c1[NH1];

static __device__ __forceinline__ unsigned fkey(float f) {
    unsigned u = __float_as_uint(f);
    return (u & 0x80000000u) ? ~u : (u | 0x80000000u);
}
static __device__ __forceinline__ float funkey(unsigned u) {
    return __uint_as_float((u & 0x80000000u) ? (u ^ 0x80000000u) : ~u);
}
static __device__ __forceinline__ void adf_relu(float m, float v, float &om, float &ov) {
    float sd  = sqrtf(v);
    float r   = m / sd;
    float cdf = 0.5f * (1.0f + erff(r * 0.7071067811865476f));
    float pdf = 0.3989422804014327f * expf(-0.5f * r * r);
    float o   = m * cdf + sd * pdf;
    om = o;
    ov = (m * m + v) * cdf + m * sd * pdf - o * o;
}
static __device__ __forceinline__ unsigned bfpack(float x, float y) {
    __nv_bfloat162 t = __floats2bfloat162_rn(x, y);
    return *(unsigned *)&t;
}
static __device__ __forceinline__ float bfi(float x) {
    return __bfloat162float(__float2bfloat16_rn(x));
}
static __device__ __forceinline__ void fma2(u64t &d, u64t a, u64t b) {
    asm("fma.rn.f32x2 %0, %1, %2, %0;" : "+l"(d) : "l"(a), "l"(b));
}
static __device__ __forceinline__ u64t dup2(float f) {
    u64t d; unsigned u = __float_as_uint(f);
    asm("mov.b64 %0, {%1, %1};" : "=l"(d) : "r"(u));
    return d;
}
static __device__ __forceinline__ void unpack2(u64t p, float &lo, float &hi) {
    unsigned a, b;
    asm("mov.b64 {%0, %1}, %2;" : "=r"(a), "=r"(b) : "l"(p));
    lo = __uint_as_float(a); hi = __uint_as_float(b);
}

// bf16 warp MMA: D(16x8,f32) += A(16x16,bf16,row) * B(8x16,bf16 [n][k])
static __device__ __forceinline__ void hmma(float *d, const unsigned *a, const unsigned *b) {
    asm volatile("mma.sync.aligned.m16n8k16.row.col.f32.bf16.bf16.f32 "
        "{%0,%1,%2,%3}, {%4,%5,%6,%7}, {%8,%9}, {%0,%1,%2,%3};"
        : "+f"(d[0]), "+f"(d[1]), "+f"(d[2]), "+f"(d[3])
        : "r"(a[0]), "r"(a[1]), "r"(a[2]), "r"(a[3]), "r"(b[0]), "r"(b[1]));
}

// ---------------- small kernels ----------------
__global__ void k_init() { g_min_u = 0xFFFFFFFFu; g_max_u = 0u; }

__global__ __launch_bounds__(256) void k_minmax(const float4 *__restrict__ x, int n4) {
    unsigned lmin = 0xFFFFFFFFu, lmax = 0u;
    for (int i = blockIdx.x * blockDim.x + threadIdx.x; i < n4; i += gridDim.x * blockDim.x) {
        float4 v = x[i];
        unsigned k0 = fkey(v.x), k1 = fkey(v.y), k2 = fkey(v.z), k3 = fkey(v.w);
        lmin = min(lmin, min(min(k0, k1), min(k2, k3)));
        lmax = max(lmax, max(max(k0, k1), max(k2, k3)));
    }
    lmin = __reduce_min_sync(0xFFFFFFFFu, lmin);
    lmax = __reduce_max_sync(0xFFFFFFFFu, lmax);
    __shared__ unsigned smin[8], smax[8];
    int wid = threadIdx.x >> 5, lane = threadIdx.x & 31;
    if (lane == 0) { smin[wid] = lmin; smax[wid] = lmax; }
    __syncthreads();
    if (threadIdx.x == 0) {
        unsigned m = smin[0], M = smax[0];
        #pragma unroll
        for (int i = 1; i < 8; i++) { m = min(m, smin[i]); M = max(M, smax[i]); }
        atomicMin(&g_min_u, m);
        atomicMax(&g_max_u, M);
    }
}

__global__ __launch_bounds__(128) void k_w1stats(const float *__restrict__ W1) {
    int h = blockIdx.x;
    const float *row = W1 + (size_t)h * SS;
    float s = 0.f, q = 0.f;
    for (int k = threadIdx.x; k < SS; k += 128) { float w = row[k]; s += w; q += w * w; }
    #pragma unroll
    for (int o = 16; o; o >>= 1) {
        s += __shfl_xor_sync(0xFFFFFFFFu, s, o);
        q += __shfl_xor_sync(0xFFFFFFFFu, q, o);
    }
    __shared__ float ss[4], qq[4];
    int wid = threadIdx.x >> 5;
    if ((threadIdx.x & 31) == 0) { ss[wid] = s; qq[wid] = q; }
    __syncthreads();
    if (threadIdx.x == 0) {
        g_s1[h] = ss[0] + ss[1] + ss[2] + ss[3];
        g_c1[h] = 2.0001f * (qq[0] + qq[1] + qq[2] + qq[3]);
    }
}

__global__ __launch_bounds__(256) void k_w2split(const float *__restrict__ W2) {
    int idx = blockIdx.x * 256 + threadIdx.x;
    if (idx >= NROWS * KPAD) return;
    int j = idx / KPAD, k = idx % KPAD;
    float w = (j < NH2 && k < NH1) ? W2[j * NH1 + k] : 0.f;
    float wq = w * w;
    g_W2h[idx]  = __float2bfloat16_rn(w);
    g_W2l[idx]  = __float2bfloat16_rn(w - bfi(w));
    g_W2qh[idx] = __float2bfloat16_rn(wq);
    g_W2ql[idx] = __float2bfloat16_rn(wq - bfi(wq));
}

// zero the pad columns (400..415) of the split-bf16 activation arrays
__global__ __launch_bounds__(256) void k_padz() {
    int idx = blockIdx.x * 256 + threadIdx.x;
    if (idx >= BB * 16) return;
    size_t off = (size_t)(idx >> 4) * KPAD + 400 + (idx & 15);
    __nv_bfloat16 z = __float2bfloat16_rn(0.f);
    g_m1h[off] = z; g_m1l[off] = z; g_v1h[off] = z; g_v1l[off] = z;
}

// pack mask1 nonzero-bits: one warp per (sample,row)
__global__ __launch_bounds__(256) void k_maskpack(const float *__restrict__ mask1) {
    int gw = blockIdx.x * 8 + (threadIdx.x >> 5);
    int lane = threadIdx.x & 31;
    if (gw >= NSAMP * BB) return;
    const float *rp = mask1 + (size_t)gw * NH1;
    #pragma unroll
    for (int g = 0; g < MWORDS; g++) {
        int k = g * 32 + lane;
        float v = (k < NH1) ? rp[k] : 0.f;
        unsigned b = __ballot_sync(0xFFFFFFFFu, v != 0.f);
        if (lane == 0) g_mk1[(size_t)gw * MWORDS + g] = b;
    }
}

// ---------------- GEMM1 (SIMT FFMA2) -> split-bf16 activations ----------------
__global__ __launch_bounds__(256) void k_gemm1(const float *__restrict__ x,
                                               const float *__restrict__ W1,
                                               const float *__restrict__ b1) {
    __shared__ float As[16 * 128];
    __shared__ float Bs[16 * 64];
    int tid = threadIdx.x;
    int tx = tid & 15, ty = tid >> 4;
    int rowBase = blockIdx.x * 128;
    int colBase = blockIdx.y * 64;

    u64t accp[4][4];
    #pragma unroll
    for (int p = 0; p < 4; p++)
        #pragma unroll
        for (int j = 0; j < 4; j++) accp[p][j] = 0ull;

    int ar = tid >> 2;
    int ak = (tid & 3) * 4;

    for (int k0 = 0; k0 < SS; k0 += 16) {
        float4 a0 = *(const float4 *)(x + (size_t)(rowBase + ar) * SS + k0 + ak);
        float4 a1 = *(const float4 *)(x + (size_t)(rowBase + ar + 64) * SS + k0 + ak);
        int j = colBase + ar;
        float4 b0 = make_float4(0.f, 0.f, 0.f, 0.f);
        if (j < NH1) b0 = *(const float4 *)(W1 + (size_t)j * SS + k0 + ak);
        __syncthreads();
        As[(ak + 0) * 128 + ar] = a0.x;
        As[(ak + 1) * 128 + ar] = a0.y;
        As[(ak + 2) * 128 + ar] = a0.z;
        As[(ak + 3) * 128 + ar] = a0.w;
        As[(ak + 0) * 128 + ar + 64] = a1.x;
        As[(ak + 1) * 128 + ar + 64] = a1.y;
        As[(ak + 2) * 128 + ar + 64] = a1.z;
        As[(ak + 3) * 128 + ar + 64] = a1.w;
        Bs[(ak + 0) * 64 + ar] = b0.x;
        Bs[(ak + 1) * 64 + ar] = b0.y;
        Bs[(ak + 2) * 64 + ar] = b0.z;
        Bs[(ak + 3) * 64 + ar] = b0.w;
        __syncthreads();
        #pragma unroll
        for (int kk = 0; kk < 16; kk++) {
            ulonglong2 A0 = *(ulonglong2 *)&As[kk * 128 + ty * 8];
            ulonglong2 A1 = *(ulonglong2 *)&As[kk * 128 + ty * 8 + 4];
            float4 tb = *(float4 *)&Bs[kk * 64 + tx * 4];
            u64t rap[4] = {A0.x, A0.y, A1.x, A1.y};
            u64t rb[4] = {dup2(tb.x), dup2(tb.y), dup2(tb.z), dup2(tb.w)};
            #pragma unroll
            for (int p = 0; p < 4; p++)
                #pragma unroll
                for (int jj = 0; jj < 4; jj++) fma2(accp[p][jj], rap[p], rb[jj]);
        }
    }

    float acc[8][4];
    #pragma unroll
    for (int p = 0; p < 4; p++)
        #pragma unroll
        for (int j = 0; j < 4; j++) unpack2(accp[p][j], acc[2 * p][j], acc[2 * p + 1][j]);

    float fmin = funkey(g_min_u);
    float fmax = funkey(g_max_u);
    float a_ = 1.0f / (fmax - fmin);
    float c_ = 0.1f - fmin * a_;

    int col = colBase + tx * 4;
    if (col < NH1) {
        #pragma unroll
        for (int i = 0; i < 8; i++) {
            int r = rowBase + ty * 8 + i;
            float om[4], ov[4];
            #pragma unroll
            for (int jj = 0; jj < 4; jj++) {
                int h = col + jj;
                float m = a_ * acc[i][jj] + c_ * g_s1[h] + b1[h];
                adf_relu(m, g_c1[h], om[jj], ov[jj]);
            }
            size_t off = (size_t)r * KPAD + col;
            uint2 mh = make_uint2(bfpack(om[0], om[1]), bfpack(om[2], om[3]));
            uint2 ml = make_uint2(bfpack(om[0] - bfi(om[0]), om[1] - bfi(om[1])),
                                  bfpack(om[2] - bfi(om[2]), om[3] - bfi(om[3])));
            uint2 vh = make_uint2(bfpack(ov[0], ov[1]), bfpack(ov[2], ov[3]));
            uint2 vl = make_uint2(bfpack(ov[0] - bfi(ov[0]), ov[1] - bfi(ov[1])),
                                  bfpack(ov[2] - bfi(ov[2]), ov[3] - bfi(ov[3])));
            *(uint2 *)&g_m1h[off] = mh;
            *(uint2 *)&g_m1l[off] = ml;
            *(uint2 *)&g_v1h[off] = vh;
            *(uint2 *)&g_v1l[off] = vl;
        }
    }
}

// ---------------- GEMM2: warp MMA, mask via bit-AND, KC=32 ----------------
// A tiles [128][KC] bf16, row stride 80B; B tiles [64][KC], stride 80B.
#define AM_H  0
#define AM_L  10240
#define AV_H  20480
#define AV_L  30720
#define BS_H  40960
#define BS_L  46080
#define BS_QH 51200
#define BS_QL 56320
#define XV    0
#define XM    34816
#define SW3S  69632
#define SW3Q  71680
#define SB2S  73728
#define G2_SMEM 74240

__global__ __launch_bounds__(256, 2) void k_gemm2_mma(const float *__restrict__ mask2,
                                                      const float *__restrict__ b2,
                                                      const float *__restrict__ W3) {
    extern __shared__ char smem[];
    int tid = threadIdx.x, w = tid >> 5, l = tid & 31;
    int blk = blockIdx.x, n = blockIdx.y;
    int rowBase = blockIdx.z * 128, colBase = blk * NB;

    float *W3s = (float *)(smem + SW3S);
    float *W3q = (float *)(smem + SW3Q);
    float *b2s = (float *)(smem + SB2S);
    for (int i = tid; i < NAOUT * NB; i += 256) {
        int a = i >> 6, c = i & 63;
        float wv = (colBase + c < NH2) ? W3[a * NH2 + colBase + c] : 0.f;
        W3s[i] = wv;
        W3q[i] = wv * wv;
    }
    for (int c = tid; c < NB; c += 256)
        b2s[c] = (colBase + c < NH2) ? b2[colBase + c] : 0.f;

    // A producer: thread -> (row = tid/2, k-half = (tid&1)*16 elems)
    int prow = tid >> 1, pkh = (tid & 1) * 16;
    size_t aoff = (size_t)(rowBase + prow) * KPAD + pkh;
    const unsigned *mkrow = g_mk1 + ((size_t)n * BB + rowBase + prow) * MWORDS;
    uint32_t pA = (uint32_t)(prow * 80 + pkh * 2);

    // B producer: thread -> (array = tid/64, brow = tid%64)
    int barr = tid >> 6, brow = tid & 63;
    const __nv_bfloat16 *bsrc;
    uint32_t bdst;
    {
        const __nv_bfloat16 *gs0 = (barr == 0) ? g_W2h : (barr == 1) ? g_W2l : (barr == 2) ? g_W2qh : g_W2ql;
        const uint32_t bd0 = (barr == 0) ? BS_H : (barr == 1) ? BS_L : (barr == 2) ? BS_QH : BS_QL;
        bsrc = gs0 + (size_t)(colBase + brow) * KPAD;
        bdst = bd0 + (uint32_t)(brow * 80);
    }

    int path = w >> 2, wr = w & 3;
    uint32_t aH = path ? AV_H : AM_H, aL = path ? AV_L : AM_L;
    uint32_t bH = path ? BS_QH : BS_H, bL = path ? BS_QL : BS_L;
    uint32_t fr = (uint32_t)(l >> 2), fc4 = (uint32_t)((l & 3) * 4);
    uint32_t aOff = (uint32_t)((wr * 32 + fr) * 80) + fc4;   // + mt*1280 + s*32
    uint32_t bOff = fr * 80 + fc4;                            // + ct*640 + s*32

    float acc[2][8][4];
    #pragma unroll
    for (int mt = 0; mt < 2; mt++)
        #pragma unroll
        for (int ct = 0; ct < 8; ct++)
            #pragma unroll
            for (int e = 0; e < 4; e++) acc[mt][ct][e] = 0.f;

    for (int ch = 0; ch < NCH; ch++) {
        // ---- produce A: load split bf16, AND with mask bits ----
        {
            unsigned mbits = mkrow[ch];
            unsigned bits16 = (pkh ? (mbits >> 16) : mbits) & 0xFFFFu;
            uint4 mh0 = *(const uint4 *)(g_m1h + aoff);
            uint4 mh1 = *(const uint4 *)(g_m1h + aoff + 8);
            uint4 ml0 = *(const uint4 *)(g_m1l + aoff);
            uint4 ml1 = *(const uint4 *)(g_m1l + aoff + 8);
            uint4 vh0 = *(const uint4 *)(g_v1h + aoff);
            uint4 vh1 = *(const uint4 *)(g_v1h + aoff + 8);
            uint4 vl0 = *(const uint4 *)(g_v1l + aoff);
            uint4 vl1 = *(const uint4 *)(g_v1l + aoff + 8);
            unsigned mw[8];
            #pragma unroll
            for (int j = 0; j < 8; j++) {
                unsigned b = (bits16 >> (2 * j)) & 3u;
                mw[j] = ((b & 1u) ? 0x0000FFFFu : 0u) | ((b & 2u) ? 0xFFFF0000u : 0u);
            }
            *(uint4 *)(smem + AM_H + pA)      = make_uint4(mh0.x & mw[0], mh0.y & mw[1], mh0.z & mw[2], mh0.w & mw[3]);
            *(uint4 *)(smem + AM_H + pA + 16) = make_uint4(mh1.x & mw[4], mh1.y & mw[5], mh1.z & mw[6], mh1.w & mw[7]);
            *(uint4 *)(smem + AM_L + pA)      = make_uint4(ml0.x & mw[0], ml0.y & mw[1], ml0.z & mw[2], ml0.w & mw[3]);
            *(uint4 *)(smem + AM_L + pA + 16) = make_uint4(ml1.x & mw[4], ml1.y & mw[5], ml1.z & mw[6], ml1.w & mw[7]);
            *(uint4 *)(smem + AV_H + pA)      = make_uint4(vh0.x & mw[0], vh0.y & mw[1], vh0.z & mw[2], vh0.w & mw[3]);
            *(uint4 *)(smem + AV_H + pA + 16) = make_uint4(vh1.x & mw[4], vh1.y & mw[5], vh1.z & mw[6], vh1.w & mw[7]);
            *(uint4 *)(smem + AV_L + pA)      = make_uint4(vl0.x & mw[0], vl0.y & mw[1], vl0.z & mw[2], vl0.w & mw[3]);
            *(uint4 *)(smem + AV_L + pA + 16) = make_uint4(vl1.x & mw[4], vl1.y & mw[5], vl1.z & mw[6], vl1.w & mw[7]);
            aoff += KC;
        }
        // ---- produce B ----
        {
            const __nv_bfloat16 *bp = bsrc + ch * KC;
            uint4 q0 = *(const uint4 *)(bp);
            uint4 q1 = *(const uint4 *)(bp + 8);
            uint4 q2 = *(const uint4 *)(bp + 16);
            uint4 q3 = *(const uint4 *)(bp + 24);
            *(uint4 *)(smem + bdst)      = q0;
            *(uint4 *)(smem + bdst + 16) = q1;
            *(uint4 *)(smem + bdst + 32) = q2;
            *(uint4 *)(smem + bdst + 48) = q3;
        }
        __syncthreads();
        // ---- MMA: 2 k-steps of 16 ----
        #pragma unroll
        for (int s = 0; s < 2; s++) {
            uint32_t so = (uint32_t)(s * 32);
            unsigned ah[2][4], al[2][4];
            #pragma unroll
            for (int mt = 0; mt < 2; mt++) {
                uint32_t ad = aOff + so + (uint32_t)(mt * 1280);
                ah[mt][0] = *(unsigned *)(smem + aH + ad);
                ah[mt][1] = *(unsigned *)(smem + aH + ad + 640);
                ah[mt][2] = *(unsigned *)(smem + aH + ad + 16);
                ah[mt][3] = *(unsigned *)(smem + aH + ad + 656);
                al[mt][0] = *(unsigned *)(smem + aL + ad);
                al[mt][1] = *(unsigned *)(smem + aL + ad + 640);
                al[mt][2] = *(unsigned *)(smem + aL + ad + 16);
                al[mt][3] = *(unsigned *)(smem + aL + ad + 656);
            }
            #pragma unroll
            for (int ct = 0; ct < 8; ct++) {
                uint32_t bd = bOff + so + (uint32_t)(ct * 640);
                unsigned bhf[2], blf[2];
                bhf[0] = *(unsigned *)(smem + bH + bd);
                bhf[1] = *(unsigned *)(smem + bH + bd + 16);
                blf[0] = *(unsigned *)(smem + bL + bd);
                blf[1] = *(unsigned *)(smem + bL + bd + 16);
                #pragma unroll
                for (int mt = 0; mt < 2; mt++) {
                    hmma(acc[mt][ct], ah[mt], bhf);
                    hmma(acc[mt][ct], al[mt], bhf);
                    hmma(acc[mt][ct], ah[mt], blf);
                }
            }
        }
        __syncthreads();
    }

    // dump accumulators to exchange region (m -> XM, v -> XV)
    {
        float *Xp = (float *)(smem + (path ? XV : XM));
        #pragma unroll
        for (int mt = 0; mt < 2; mt++)
            #pragma unroll
            for (int ct = 0; ct < 8; ct++) {
                int r0 = wr * 32 + mt * 16 + (int)fr;
                int c0 = ct * 8 + (l & 3) * 2;
                *(float2 *)&Xp[r0 * 68 + c0] = make_float2(acc[mt][ct][0], acc[mt][ct][1]);
                *(float2 *)&Xp[(r0 + 8) * 68 + c0] = make_float2(acc[mt][ct][2], acc[mt][ct][3]);
            }
    }
    __syncthreads();

    // epilogue: scale (fold 1/0.9, 1/0.81), ADF, mask2, W3 contraction
    {
        const float INV09 = 1.0f / 0.9f;
        const float INV081 = (1.0f / 0.9f) * (1.0f / 0.9f);
        int erow = w * 16 + (l >> 1), ecol0 = (l & 1) * 32;
        const float *Xm = (const float *)(smem + XM);
        const float *Xv = (const float *)(smem + XV);
        const float *m2r = mask2 + ((size_t)n * BB + rowBase + erow) * NH2 + colBase;
        float pm[NAOUT], pv[NAOUT];
        #pragma unroll
        for (int a = 0; a < NAOUT; a++) { pm[a] = 0.f; pv[a] = 0.f; }
        #pragma unroll 4
        for (int c = 0; c < 32; c++) {
            int cc = ecol0 + c;
            if (colBase + cc < NH2) {
                float m = Xm[erow * 68 + cc] * INV09 + b2s[cc];
                float v = Xv[erow * 68 + cc] * INV081;
                float om, ov;
                adf_relu(m, v, om, ov);
                float q = __ldg(m2r + cc);
                float am = om * q, av = ov * q * q;
                #pragma unroll
                for (int a = 0; a < NAOUT; a++) {
                    pm[a] += am * W3s[a * NB + cc];
                    pv[a] += av * W3q[a * NB + cc];
                }
            }
        }
        #pragma unroll
        for (int a = 0; a < NAOUT; a++) {
            pm[a] += __shfl_xor_sync(0xFFFFFFFFu, pm[a], 1);
            pv[a] += __shfl_xor_sync(0xFFFFFFFFu, pv[a], 1);
        }
        if ((l & 1) == 0) {
            size_t base = (((size_t)n * NBLK + blk) * BB + rowBase + erow) * NAOUT;
            *(float4 *)&g_Pm[base + 0] = make_float4(pm[0], pm[1], pm[2], pm[3]);
            *(float4 *)&g_Pm[base + 4] = make_float4(pm[4], pm[5], pm[6], pm[7]);
            *(float4 *)&g_Pv[base + 0] = make_float4(pv[0], pv[1], pv[2], pv[3]);
            *(float4 *)&g_Pv[base + 4] = make_float4(pv[4], pv[5], pv[6], pv[7]);
        }
    }
}

// ---------------- final reduction ----------------
__global__ __launch_bounds__(256) void k_final(const float *__restrict__ b3,
                                               float *__restrict__ out) {
    int i = blockIdx.x * 256 + threadIdx.x;
    if (i >= BB * NAOUT) return;
    int b = i >> 3, a = i & 7;
    float s1 = 0.f, s2 = 0.f, sv = 0.f;
    float bb3 = b3[a];
    #pragma unroll
    for (int n = 0; n < NSAMP; n++) {
        float m3 = bb3, v3 = 0.f;
        #pragma unroll
        for (int blk = 0; blk < NBLK; blk++) {
            size_t idx = (((size_t)n * NBLK + blk) * BB + b) * NAOUT + a;
            m3 += g_Pm[idx];
            v3 += g_Pv[idx];
        }
        s1 += m3;
        s2 += m3 * m3;
        sv += v3;
    }
    const float inv3 = 1.0f / 3.0f;
    float mean = s1 * inv3;
    float var = sv * inv3 + s2 * inv3 - mean * mean;
    out[(size_t)b * NAOUT + a] = mean;
    out[(size_t)BB * NAOUT + (size_t)b * NAOUT + a] = exp10f(var);
}

// ---------------- launch ----------------
extern "C" void kernel_launch(void *const *d_in, const int *in_sizes, int n_in,
                              void *d_out, int out_size) {
    const float *x  = (const float *)d_in[0];
    const float *W1 = (const float *)d_in[2];
    const float *b1 = (const float *)d_in[3];
    const float *W2 = (const float *)d_in[4];
    const float *b2 = (const float *)d_in[5];
    const float *W3 = (const float *)d_in[6];
    const float *b3 = (const float *)d_in[7];
    const float *mask1 = (const float *)d_in[8];
    const float *mask2 = (const float *)d_in[9];
    float *out = (float *)d_out;

    cudaFuncSetAttribute(k_gemm2_mma, cudaFuncAttributeMaxDynamicSharedMemorySize, G2_SMEM);

    k_init<<<1, 1>>>();
    k_minmax<<<2048, 256>>>((const float4 *)x, BB * SS / 4);
    k_w1stats<<<NH1, 128>>>(W1);
    k_w2split<<<(NROWS * KPAD + 255) / 256, 256>>>(W2);
    k_padz<<<(BB * 16 + 255) / 256, 256>>>();
    k_maskpack<<<(NSAMP * BB + 7) / 8, 256>>>(mask1);
    dim3 g1(BB / 128, (NH1 + 63) / 64);
    k_gemm1<<<g1, 256>>>(x, W1, b1);
    dim3 g2(NBLK, NSAMP, BB / 128);
    k_gemm2_mma<<<g2, 256, G2_SMEM>>>(mask2, b2, W3);
    k_final<<<BB * NAOUT / 256, 256>>>(b3, out);
}

// round 17
// speedup vs baseline: 1.8303x; 1.0466x over previous
#include <cuda_runtime.h>
#include <cuda_bf16.h>
#include <math.h>
#include <stdint.h>

#define BB 32768
#define SS 512
#define NH1 400
#define NH2 300
#define NAOUT 8
#define NSAMP 3
#define KPAD 416      // 13 * 32
#define NB 64         // cols per CTA
#define NBLK 5        // 5*64 = 320 >= 300
#define NROWS 320
#define NCH 13        // K chunks of 32
#define KC 32
#define MWORDS 13     // mask words per row (416 bits)

typedef unsigned long long u64t;

// ---------------- scratch ----------------
static __device__ __nv_bfloat16 g_m1h[(size_t)BB * KPAD];
static __device__ __nv_bfloat16 g_m1l[(size_t)BB * KPAD];
static __device__ __nv_bfloat16 g_v1h[(size_t)BB * KPAD];
static __device__ __nv_bfloat16 g_v1l[(size_t)BB * KPAD];
static __device__ unsigned g_mk1[(size_t)NSAMP * BB * MWORDS];
static __device__ __nv_bfloat16 g_W2h[NROWS * KPAD];
static __device__ __nv_bfloat16 g_W2l[NROWS * KPAD];
static __device__ __nv_bfloat16 g_W2qh[NROWS * KPAD];
static __device__ __nv_bfloat16 g_W2ql[NROWS * KPAD];
static __device__ float g_Pm[(size_t)NSAMP * NBLK * BB * NAOUT];
static __device__ float g_Pv[(size_t)NSAMP * NBLK * BB * NAOUT];
static __device__ unsigned g_min_u, g_max_u;
static __device__ float g_s1[NH1];
static __device__ float g_c1[NH1];

static __device__ __forceinline__ unsigned fkey(float f) {
    unsigned u = __float_as_uint(f);
    return (u & 0x80000000u) ? ~u : (u | 0x80000000u);
}
static __device__ __forceinline__ float funkey(unsigned u) {
    return __uint_as_float((u & 0x80000000u) ? (u ^ 0x80000000u) : ~u);
}
static __device__ __forceinline__ void adf_relu(float m, float v, float &om, float &ov) {
    float sd  = sqrtf(v);
    float r   = m / sd;
    float cdf = 0.5f * (1.0f + erff(r * 0.7071067811865476f));
    float pdf = 0.3989422804014327f * expf(-0.5f * r * r);
    float o   = m * cdf + sd * pdf;
    om = o;
    ov = (m * m + v) * cdf + m * sd * pdf - o * o;
}
static __device__ __forceinline__ unsigned bfpack(float x, float y) {
    __nv_bfloat162 t = __floats2bfloat162_rn(x, y);
    return *(unsigned *)&t;
}
static __device__ __forceinline__ float bfi(float x) {
    return __bfloat162float(__float2bfloat16_rn(x));
}
static __device__ __forceinline__ void fma2(u64t &d, u64t a, u64t b) {
    asm("fma.rn.f32x2 %0, %1, %2, %0;" : "+l"(d) : "l"(a), "l"(b));
}
static __device__ __forceinline__ u64t dup2(float f) {
    u64t d; unsigned u = __float_as_uint(f);
    asm("mov.b64 %0, {%1, %1};" : "=l"(d) : "r"(u));
    return d;
}
static __device__ __forceinline__ void unpack2(u64t p, float &lo, float &hi) {
    unsigned a, b;
    asm("mov.b64 {%0, %1}, %2;" : "=r"(a), "=r"(b) : "l"(p));
    lo = __uint_as_float(a); hi = __uint_as_float(b);
}

// bf16 warp MMA: D(16x8,f32) += A(16x16,bf16,row) * B(8x16,bf16 [n][k])
static __device__ __forceinline__ void hmma(float *d, const unsigned *a, const unsigned *b) {
    asm volatile("mma.sync.aligned.m16n8k16.row.col.f32.bf16.bf16.f32 "
        "{%0,%1,%2,%3}, {%4,%5,%6,%7}, {%8,%9}, {%0,%1,%2,%3};"
        : "+f"(d[0]), "+f"(d[1]), "+f"(d[2]), "+f"(d[3])
        : "r"(a[0]), "r"(a[1]), "r"(a[2]), "r"(a[3]), "r"(b[0]), "r"(b[1]));
}
#define LDSM_X4(r0, r1, r2, r3, addr) \
    asm volatile("ldmatrix.sync.aligned.m8n8.x4.shared.b16 {%0,%1,%2,%3}, [%4];" \
        : "=r"(r0), "=r"(r1), "=r"(r2), "=r"(r3) : "r"(addr))

__device__ __forceinline__ uint32_t smem_u32(const void *p) {
    uint32_t a;
    asm("{ .reg .u64 t; cvta.to.shared.u64 t, %1; cvt.u32.u64 %0, t; }" : "=r"(a) : "l"(p));
    return a;
}

// ---------------- small kernels ----------------
__global__ void k_init() { g_min_u = 0xFFFFFFFFu; g_max_u = 0u; }

__global__ __launch_bounds__(256) void k_minmax(const float4 *__restrict__ x, int n4) {
    unsigned lmin = 0xFFFFFFFFu, lmax = 0u;
    for (int i = blockIdx.x * blockDim.x + threadIdx.x; i < n4; i += gridDim.x * blockDim.x) {
        float4 v = x[i];
        unsigned k0 = fkey(v.x), k1 = fkey(v.y), k2 = fkey(v.z), k3 = fkey(v.w);
        lmin = min(lmin, min(min(k0, k1), min(k2, k3)));
        lmax = max(lmax, max(max(k0, k1), max(k2, k3)));
    }
    lmin = __reduce_min_sync(0xFFFFFFFFu, lmin);
    lmax = __reduce_max_sync(0xFFFFFFFFu, lmax);
    __shared__ unsigned smin[8], smax[8];
    int wid = threadIdx.x >> 5, lane = threadIdx.x & 31;
    if (lane == 0) { smin[wid] = lmin; smax[wid] = lmax; }
    __syncthreads();
    if (threadIdx.x == 0) {
        unsigned m = smin[0], M = smax[0];
        #pragma unroll
        for (int i = 1; i < 8; i++) { m = min(m, smin[i]); M = max(M, smax[i]); }
        atomicMin(&g_min_u, m);
        atomicMax(&g_max_u, M);
    }
}

__global__ __launch_bounds__(128) void k_w1stats(const float *__restrict__ W1) {
    int h = blockIdx.x;
    const float *row = W1 + (size_t)h * SS;
    float s = 0.f, q = 0.f;
    for (int k = threadIdx.x; k < SS; k += 128) { float w = row[k]; s += w; q += w * w; }
    #pragma unroll
    for (int o = 16; o; o >>= 1) {
        s += __shfl_xor_sync(0xFFFFFFFFu, s, o);
        q += __shfl_xor_sync(0xFFFFFFFFu, q, o);
    }
    __shared__ float ss[4], qq[4];
    int wid = threadIdx.x >> 5;
    if ((threadIdx.x & 31) == 0) { ss[wid] = s; qq[wid] = q; }
    __syncthreads();
    if (threadIdx.x == 0) {
        g_s1[h] = ss[0] + ss[1] + ss[2] + ss[3];
        g_c1[h] = 2.0001f * (qq[0] + qq[1] + qq[2] + qq[3]);
    }
}

// merged prep: W2 split | pad zero | mask pack  (keeps gemm2 at launch index 5 for ncu)
#define PREP_W2_BLKS 520       // NROWS*KPAD/256
#define PREP_PAD_BLKS 2048     // BB*16/256
#define PREP_MK_BLKS 12288     // NSAMP*BB/8
__global__ __launch_bounds__(256) void k_prep(const float *__restrict__ W2,
                                              const float *__restrict__ mask1) {
    int b = blockIdx.x, tid = threadIdx.x;
    if (b < PREP_W2_BLKS) {
        int idx = b * 256 + tid;
        if (idx < NROWS * KPAD) {
            int j = idx / KPAD, k = idx % KPAD;
            float w = (j < NH2 && k < NH1) ? W2[j * NH1 + k] : 0.f;
            float wq = w * w;
            g_W2h[idx]  = __float2bfloat16_rn(w);
            g_W2l[idx]  = __float2bfloat16_rn(w - bfi(w));
            g_W2qh[idx] = __float2bfloat16_rn(wq);
            g_W2ql[idx] = __float2bfloat16_rn(wq - bfi(wq));
        }
    } else if (b < PREP_W2_BLKS + PREP_PAD_BLKS) {
        int idx = (b - PREP_W2_BLKS) * 256 + tid;
        if (idx < BB * 16) {
            size_t off = (size_t)(idx >> 4) * KPAD + 400 + (idx & 15);
            __nv_bfloat16 z = __float2bfloat16_rn(0.f);
            g_m1h[off] = z; g_m1l[off] = z; g_v1h[off] = z; g_v1l[off] = z;
        }
    } else {
        int gw = (b - PREP_W2_BLKS - PREP_PAD_BLKS) * 8 + (tid >> 5);
        int lane = tid & 31;
        if (gw < NSAMP * BB) {
            const float *rp = mask1 + (size_t)gw * NH1;
            #pragma unroll
            for (int g = 0; g < MWORDS; g++) {
                int k = g * 32 + lane;
                float v = (k < NH1) ? rp[k] : 0.f;
                unsigned bb = __ballot_sync(0xFFFFFFFFu, v != 0.f);
                if (lane == 0) g_mk1[(size_t)gw * MWORDS + g] = bb;
            }
        }
    }
}

// ---------------- GEMM1 (SIMT FFMA2) -> split-bf16 activations ----------------
__global__ __launch_bounds__(256) void k_gemm1(const float *__restrict__ x,
                                               const float *__restrict__ W1,
                                               const float *__restrict__ b1) {
    __shared__ float As[16 * 128];
    __shared__ float Bs[16 * 64];
    int tid = threadIdx.x;
    int tx = tid & 15, ty = tid >> 4;
    int rowBase = blockIdx.x * 128;
    int colBase = blockIdx.y * 64;

    u64t accp[4][4];
    #pragma unroll
    for (int p = 0; p < 4; p++)
        #pragma unroll
        for (int j = 0; j < 4; j++) accp[p][j] = 0ull;

    int ar = tid >> 2;
    int ak = (tid & 3) * 4;

    for (int k0 = 0; k0 < SS; k0 += 16) {
        float4 a0 = *(const float4 *)(x + (size_t)(rowBase + ar) * SS + k0 + ak);
        float4 a1 = *(const float4 *)(x + (size_t)(rowBase + ar + 64) * SS + k0 + ak);
        int j = colBase + ar;
        float4 b0 = make_float4(0.f, 0.f, 0.f, 0.f);
        if (j < NH1) b0 = *(const float4 *)(W1 + (size_t)j * SS + k0 + ak);
        __syncthreads();
        As[(ak + 0) * 128 + ar] = a0.x;
        As[(ak + 1) * 128 + ar] = a0.y;
        As[(ak + 2) * 128 + ar] = a0.z;
        As[(ak + 3) * 128 + ar] = a0.w;
        As[(ak + 0) * 128 + ar + 64] = a1.x;
        As[(ak + 1) * 128 + ar + 64] = a1.y;
        As[(ak + 2) * 128 + ar + 64] = a1.z;
        As[(ak + 3) * 128 + ar + 64] = a1.w;
        Bs[(ak + 0) * 64 + ar] = b0.x;
        Bs[(ak + 1) * 64 + ar] = b0.y;
        Bs[(ak + 2) * 64 + ar] = b0.z;
        Bs[(ak + 3) * 64 + ar] = b0.w;
        __syncthreads();
        #pragma unroll
        for (int kk = 0; kk < 16; kk++) {
            ulonglong2 A0 = *(ulonglong2 *)&As[kk * 128 + ty * 8];
            ulonglong2 A1 = *(ulonglong2 *)&As[kk * 128 + ty * 8 + 4];
            float4 tb = *(float4 *)&Bs[kk * 64 + tx * 4];
            u64t rap[4] = {A0.x, A0.y, A1.x, A1.y};
            u64t rb[4] = {dup2(tb.x), dup2(tb.y), dup2(tb.z), dup2(tb.w)};
            #pragma unroll
            for (int p = 0; p < 4; p++)
                #pragma unroll
                for (int jj = 0; jj < 4; jj++) fma2(accp[p][jj], rap[p], rb[jj]);
        }
    }

    float acc[8][4];
    #pragma unroll
    for (int p = 0; p < 4; p++)
        #pragma unroll
        for (int j = 0; j < 4; j++) unpack2(accp[p][j], acc[2 * p][j], acc[2 * p + 1][j]);

    float fmin = funkey(g_min_u);
    float fmax = funkey(g_max_u);
    float a_ = 1.0f / (fmax - fmin);
    float c_ = 0.1f - fmin * a_;

    int col = colBase + tx * 4;
    if (col < NH1) {
        #pragma unroll
        for (int i = 0; i < 8; i++) {
            int r = rowBase + ty * 8 + i;
            float om[4], ov[4];
            #pragma unroll
            for (int jj = 0; jj < 4; jj++) {
                int h = col + jj;
                float m = a_ * acc[i][jj] + c_ * g_s1[h] + b1[h];
                adf_relu(m, g_c1[h], om[jj], ov[jj]);
            }
            size_t off = (size_t)r * KPAD + col;
            uint2 mh = make_uint2(bfpack(om[0], om[1]), bfpack(om[2], om[3]));
            uint2 ml = make_uint2(bfpack(om[0] - bfi(om[0]), om[1] - bfi(om[1])),
                                  bfpack(om[2] - bfi(om[2]), om[3] - bfi(om[3])));
            uint2 vh = make_uint2(bfpack(ov[0], ov[1]), bfpack(ov[2], ov[3]));
            uint2 vl = make_uint2(bfpack(ov[0] - bfi(ov[0]), ov[1] - bfi(ov[1])),
                                  bfpack(ov[2] - bfi(ov[2]), ov[3] - bfi(ov[3])));
            *(uint2 *)&g_m1h[off] = mh;
            *(uint2 *)&g_m1l[off] = ml;
            *(uint2 *)&g_v1h[off] = vh;
            *(uint2 *)&g_v1l[off] = vl;
        }
    }
}

// ---------------- GEMM2: warp MMA, ldmatrix fragments, B prefetch ----------------
#define AM_H  0
#define AM_L  10240
#define AV_H  20480
#define AV_L  30720
#define BS_H  40960
#define BS_L  46080
#define BS_QH 51200
#define BS_QL 56320
#define XV    0
#define XM    34816
#define SW3S  69632
#define SW3Q  71680
#define SB2S  73728
#define G2_SMEM 74240

__global__ __launch_bounds__(256, 2) void k_gemm2_mma(const float *__restrict__ mask2,
                                                      const float *__restrict__ b2,
                                                      const float *__restrict__ W3) {
    extern __shared__ char smem[];
    int tid = threadIdx.x, w = tid >> 5, l = tid & 31;
    int blk = blockIdx.x, n = blockIdx.y;
    int rowBase = blockIdx.z * 128, colBase = blk * NB;

    float *W3s = (float *)(smem + SW3S);
    float *W3q = (float *)(smem + SW3Q);
    float *b2s = (float *)(smem + SB2S);
    for (int i = tid; i < NAOUT * NB; i += 256) {
        int a = i >> 6, c = i & 63;
        float wv = (colBase + c < NH2) ? W3[a * NH2 + colBase + c] : 0.f;
        W3s[i] = wv;
        W3q[i] = wv * wv;
    }
    for (int c = tid; c < NB; c += 256)
        b2s[c] = (colBase + c < NH2) ? b2[colBase + c] : 0.f;

    // A producer: thread -> (row = tid/2, k-half = (tid&1)*16 elems)
    int prow = tid >> 1, pkh = (tid & 1) * 16;
    size_t aoff = (size_t)(rowBase + prow) * KPAD + pkh;
    const unsigned *mkrow = g_mk1 + ((size_t)n * BB + rowBase + prow) * MWORDS;
    uint32_t pA = (uint32_t)(prow * 80 + pkh * 2);

    // B producer: thread -> (array = tid/64, brow = tid%64)
    int barr = tid >> 6, brow = tid & 63;
    const __nv_bfloat16 *bsrc;
    uint32_t bdst;
    {
        const __nv_bfloat16 *gs0 = (barr == 0) ? g_W2h : (barr == 1) ? g_W2l : (barr == 2) ? g_W2qh : g_W2ql;
        const uint32_t bd0 = (barr == 0) ? BS_H : (barr == 1) ? BS_L : (barr == 2) ? BS_QH : BS_QL;
        bsrc = gs0 + (size_t)(colBase + brow) * KPAD;
        bdst = bd0 + (uint32_t)(brow * 80);
    }

    int path = w >> 2, wr = w & 3;
    uint32_t sbase = smem_u32(smem);
    uint32_t aH = path ? AV_H : AM_H, aL = path ? AV_L : AM_L;
    uint32_t bH = path ? BS_QH : BS_H, bL = path ? BS_QL : BS_L;
    // ldmatrix base addresses
    uint32_t aFrag = (uint32_t)((wr * 32 + (l & 15)) * 80 + ((l >> 4) & 1) * 16);
    uint32_t aAddrH = sbase + aH + aFrag;
    uint32_t aAddrL = sbase + aL + aFrag;
    uint32_t bFrag = (uint32_t)((((l >> 4) & 1) * 8 + (l & 7)) * 80 + ((l >> 3) & 1) * 16);
    uint32_t bAddrH = sbase + bH + bFrag;
    uint32_t bAddrL = sbase + bL + bFrag;

    float acc[2][8][4];
    #pragma unroll
    for (int mt = 0; mt < 2; mt++)
        #pragma unroll
        for (int ct = 0; ct < 8; ct++)
            #pragma unroll
            for (int e = 0; e < 4; e++) acc[mt][ct][e] = 0.f;

    // prefetch B chunk 0 + mask word 0
    uint4 bq0, bq1, bq2, bq3;
    {
        const __nv_bfloat16 *bp = bsrc;
        bq0 = *(const uint4 *)(bp);
        bq1 = *(const uint4 *)(bp + 8);
        bq2 = *(const uint4 *)(bp + 16);
        bq3 = *(const uint4 *)(bp + 24);
    }
    unsigned mbits = mkrow[0];

    for (int ch = 0; ch < NCH; ch++) {
        // ---- produce A: load split bf16, AND with mask bits ----
        {
            unsigned bits16 = (pkh ? (mbits >> 16) : mbits) & 0xFFFFu;
            uint4 mh0 = *(const uint4 *)(g_m1h + aoff);
            uint4 mh1 = *(const uint4 *)(g_m1h + aoff + 8);
            uint4 ml0 = *(const uint4 *)(g_m1l + aoff);
            uint4 ml1 = *(const uint4 *)(g_m1l + aoff + 8);
            uint4 vh0 = *(const uint4 *)(g_v1h + aoff);
            uint4 vh1 = *(const uint4 *)(g_v1h + aoff + 8);
            uint4 vl0 = *(const uint4 *)(g_v1l + aoff);
            uint4 vl1 = *(const uint4 *)(g_v1l + aoff + 8);
            unsigned mw[8];
            #pragma unroll
            for (int j = 0; j < 8; j++) {
                unsigned b = (bits16 >> (2 * j)) & 3u;
                mw[j] = ((b & 1u) ? 0x0000FFFFu : 0u) | ((b & 2u) ? 0xFFFF0000u : 0u);
            }
            *(uint4 *)(smem + AM_H + pA)      = make_uint4(mh0.x & mw[0], mh0.y & mw[1], mh0.z & mw[2], mh0.w & mw[3]);
            *(uint4 *)(smem + AM_H + pA + 16) = make_uint4(mh1.x & mw[4], mh1.y & mw[5], mh1.z & mw[6], mh1.w & mw[7]);
            *(uint4 *)(smem + AM_L + pA)      = make_uint4(ml0.x & mw[0], ml0.y & mw[1], ml0.z & mw[2], ml0.w & mw[3]);
            *(uint4 *)(smem + AM_L + pA + 16) = make_uint4(ml1.x & mw[4], ml1.y & mw[5], ml1.z & mw[6], ml1.w & mw[7]);
            *(uint4 *)(smem + AV_H + pA)      = make_uint4(vh0.x & mw[0], vh0.y & mw[1], vh0.z & mw[2], vh0.w & mw[3]);
            *(uint4 *)(smem + AV_H + pA + 16) = make_uint4(vh1.x & mw[4], vh1.y & mw[5], vh1.z & mw[6], vh1.w & mw[7]);
            *(uint4 *)(smem + AV_L + pA)      = make_uint4(vl0.x & mw[0], vl0.y & mw[1], vl0.z & mw[2], vl0.w & mw[3]);
            *(uint4 *)(smem + AV_L + pA + 16) = make_uint4(vl1.x & mw[4], vl1.y & mw[5], vl1.z & mw[6], vl1.w & mw[7]);
            aoff += KC;
        }
        // ---- store prefetched B ----
        *(uint4 *)(smem + bdst)      = bq0;
        *(uint4 *)(smem + bdst + 16) = bq1;
        *(uint4 *)(smem + bdst + 32) = bq2;
        *(uint4 *)(smem + bdst + 48) = bq3;
        __syncthreads();
        // ---- prefetch next B + mask (latency overlaps MMA) ----
        if (ch + 1 < NCH) {
            const __nv_bfloat16 *bp = bsrc + (ch + 1) * KC;
            bq0 = *(const uint4 *)(bp);
            bq1 = *(const uint4 *)(bp + 8);
            bq2 = *(const uint4 *)(bp + 16);
            bq3 = *(const uint4 *)(bp + 24);
            mbits = mkrow[ch + 1];
        }
        // ---- MMA: 2 k-steps of 16, ldmatrix fragments ----
        #pragma unroll
        for (int s = 0; s < 2; s++) {
            uint32_t so = (uint32_t)(s * 32);
            unsigned ah[2][4], al[2][4];
            #pragma unroll
            for (int mt = 0; mt < 2; mt++) {
                LDSM_X4(ah[mt][0], ah[mt][1], ah[mt][2], ah[mt][3], aAddrH + so + (uint32_t)(mt * 1280));
                LDSM_X4(al[mt][0], al[mt][1], al[mt][2], al[mt][3], aAddrL + so + (uint32_t)(mt * 1280));
            }
            #pragma unroll
            for (int p = 0; p < 4; p++) {
                unsigned bh[4], bl[4];
                LDSM_X4(bh[0], bh[1], bh[2], bh[3], bAddrH + so + (uint32_t)(p * 1280));
                LDSM_X4(bl[0], bl[1], bl[2], bl[3], bAddrL + so + (uint32_t)(p * 1280));
                #pragma unroll
                for (int mt = 0; mt < 2; mt++) {
                    hmma(acc[mt][2 * p], ah[mt], &bh[0]);
                    hmma(acc[mt][2 * p], al[mt], &bh[0]);
                    hmma(acc[mt][2 * p], ah[mt], &bl[0]);
                    hmma(acc[mt][2 * p + 1], ah[mt], &bh[2]);
                    hmma(acc[mt][2 * p + 1], al[mt], &bh[2]);
                    hmma(acc[mt][2 * p + 1], ah[mt], &bl[2]);
                }
            }
        }
        __syncthreads();
    }

    // dump accumulators to exchange region (m -> XM, v -> XV)
    {
        uint32_t fr = (uint32_t)(l >> 2);
        float *Xp = (float *)(smem + (path ? XV : XM));
        #pragma unroll
        for (int mt = 0; mt < 2; mt++)
            #pragma unroll
            for (int ct = 0; ct < 8; ct++) {
                int r0 = wr * 32 + mt * 16 + (int)fr;
                int c0 = ct * 8 + (l & 3) * 2;
                *(float2 *)&Xp[r0 * 68 + c0] = make_float2(acc[mt][ct][0], acc[mt][ct][1]);
                *(float2 *)&Xp[(r0 + 8) * 68 + c0] = make_float2(acc[mt][ct][2], acc[mt][ct][3]);
            }
    }
    __syncthreads();

    // epilogue: scale (fold 1/0.9, 1/0.81), ADF, mask2, W3 contraction
    {
        const float INV09 = 1.0f / 0.9f;
        const float INV081 = (1.0f / 0.9f) * (1.0f / 0.9f);
        int erow = w * 16 + (l >> 1), ecol0 = (l & 1) * 32;
        const float *Xm = (const float *)(smem + XM);
        const float *Xv = (const float *)(smem + XV);
        const float *m2r = mask2 + ((size_t)n * BB + rowBase + erow) * NH2 + colBase;
        float pm[NAOUT], pv[NAOUT];
        #pragma unroll
        for (int a = 0; a < NAOUT; a++) { pm[a] = 0.f; pv[a] = 0.f; }
        #pragma unroll 4
        for (int c = 0; c < 32; c++) {
            int cc = ecol0 + c;
            if (colBase + cc < NH2) {
                float m = Xm[erow * 68 + cc] * INV09 + b2s[cc];
                float v = Xv[erow * 68 + cc] * INV081;
                float om, ov;
                adf_relu(m, v, om, ov);
                float q = __ldg(m2r + cc);
                float am = om * q, av = ov * q * q;
                #pragma unroll
                for (int a = 0; a < NAOUT; a++) {
                    pm[a] += am * W3s[a * NB + cc];
                    pv[a] += av * W3q[a * NB + cc];
                }
            }
        }
        #pragma unroll
        for (int a = 0; a < NAOUT; a++) {
            pm[a] += __shfl_xor_sync(0xFFFFFFFFu, pm[a], 1);
            pv[a] += __shfl_xor_sync(0xFFFFFFFFu, pv[a], 1);
        }
        if ((l & 1) == 0) {
            size_t base = (((size_t)n * NBLK + blk) * BB + rowBase + erow) * NAOUT;
            *(float4 *)&g_Pm[base + 0] = make_float4(pm[0], pm[1], pm[2], pm[3]);
            *(float4 *)&g_Pm[base + 4] = make_float4(pm[4], pm[5], pm[6], pm[7]);
            *(float4 *)&g_Pv[base + 0] = make_float4(pv[0], pv[1], pv[2], pv[3]);
            *(float4 *)&g_Pv[base + 4] = make_float4(pv[4], pv[5], pv[6], pv[7]);
        }
    }
}

// ---------------- final reduction ----------------
__global__ __launch_bounds__(256) void k_final(const float *__restrict__ b3,
                                               float *__restrict__ out) {
    int i = blockIdx.x * 256 + threadIdx.x;
    if (i >= BB * NAOUT) return;
    int b = i >> 3, a = i & 7;
    float s1 = 0.f, s2 = 0.f, sv = 0.f;
    float bb3 = b3[a];
    #pragma unroll
    for (int n = 0; n < NSAMP; n++) {
        float m3 = bb3, v3 = 0.f;
        #pragma unroll
        for (int blk = 0; blk < NBLK; blk++) {
            size_t idx = (((size_t)n * NBLK + blk) * BB + b) * NAOUT + a;
            m3 += g_Pm[idx];
            v3 += g_Pv[idx];
        }
        s1 += m3;
        s2 += m3 * m3;
        sv += v3;
    }
    const float inv3 = 1.0f / 3.0f;
    float mean = s1 * inv3;
    float var = sv * inv3 + s2 * inv3 - mean * mean;
    out[(size_t)b * NAOUT + a] = mean;
    out[(size_t)BB * NAOUT + (size_t)b * NAOUT + a] = exp10f(var);
}

// ---------------- launch ----------------
extern "C" void kernel_launch(void *const *d_in, const int *in_sizes, int n_in,
                              void *d_out, int out_size) {
    const float *x  = (const float *)d_in[0];
    const float *W1 = (const float *)d_in[2];
    const float *b1 = (const float *)d_in[3];
    const float *W2 = (const float *)d_in[4];
    const float *b2 = (const float *)d_in[5];
    const float *W3 = (const float *)d_in[6];
    const float *b3 = (const float *)d_in[7];
    const float *mask1 = (const float *)d_in[8];
    const float *mask2 = (const float *)d_in[9];
    float *out = (float *)d_out;

    cudaFuncSetAttribute(k_gemm2_mma, cudaFuncAttributeMaxDynamicSharedMemorySize, G2_SMEM);

    k_init<<<1, 1>>>();
    k_minmax<<<2048, 256>>>((const float4 *)x, BB * SS / 4);
    k_w1stats<<<NH1, 128>>>(W1);
    k_prep<<<PREP_W2_BLKS + PREP_PAD_BLKS + PREP_MK_BLKS, 256>>>(W2, mask1);
    dim3 g1(BB / 128, (NH1 + 63) / 64);
    k_gemm1<<<g1, 256>>>(x, W1, b1);
    dim3 g2(NBLK, NSAMP, BB / 128);
    k_gemm2_mma<<<g2, 256, G2_SMEM>>>(mask2, b2, W3);
    k_final<<<BB * NAOUT / 256, 256>>>(b3, out);
}